// round 2
// baseline (speedup 1.0000x reference)
#include <cuda_runtime.h>
#include <cuda_bf16.h>

// RBF layer: out[n] = sum_m w[m] * exp(-(x_n - mu_m)^T (G_m G_m^T) (x_n - mu_m))
// Factorized: dist(n,m) = || G_m^T x_n - t_m ||^2 with t_m = G_m^T mu_m.
//
// N = 32768, M = 2048, D = 32 (fixed by the problem).
//
// Kernel 1: precompute t[m][e] = sum_d gamma[m][d][e] * mu[m][d]
// Kernel 2: main fused kernel. Each thread owns one row n; CTA streams gamma_m
//           tiles through shared memory (LDS.128 broadcast, 1 LDS per 4 FFMA).
//           Grid split over m (MSPLIT partial accumulators) for SM balance.
// Kernel 3: reduce partials -> out.

#define DD 32
#define NN 32768
#define MM 2048
#define MSPLIT 2
#define BLOCK 128

__device__ float g_t[MM * DD];            // t_m = G_m^T mu_m
__device__ float g_partial[MSPLIT * NN];  // partial sums over m-splits

__global__ void prep_t_kernel(const float* __restrict__ gamma,
                              const float* __restrict__ means) {
    int m = blockIdx.x;
    int e = threadIdx.x;  // 0..31
    const float* g = gamma + (size_t)m * DD * DD;
    const float* mu = means + (size_t)m * DD;
    float s = 0.0f;
#pragma unroll
    for (int d = 0; d < DD; d++) {
        s += g[d * DD + e] * mu[d];
    }
    g_t[m * DD + e] = s;
}

__global__ __launch_bounds__(BLOCK) void rbf_main_kernel(
    const float* __restrict__ x,
    const float* __restrict__ gamma,
    const float* __restrict__ weights) {
    __shared__ float4 gs[DD * (DD / 4)];  // gamma_m as [d][e/4] float4 (4 KB)
    __shared__ float4 ts[DD / 4];         // t_m

    const int tid = threadIdx.x;
    const int n = blockIdx.x * BLOCK + tid;
    const int m0 = blockIdx.y * (MM / MSPLIT);
    const int m1 = m0 + (MM / MSPLIT);

    // Load this thread's x row into registers (128 contiguous bytes).
    float xr[DD];
    {
        const float4* xp = reinterpret_cast<const float4*>(x + (size_t)n * DD);
#pragma unroll
        for (int i = 0; i < DD / 4; i++) {
            float4 v = xp[i];
            xr[4 * i + 0] = v.x;
            xr[4 * i + 1] = v.y;
            xr[4 * i + 2] = v.z;
            xr[4 * i + 3] = v.w;
        }
    }

    float acc = 0.0f;

    for (int m = m0; m < m1; ++m) {
        // Cooperative load of gamma_m (1024 floats = 256 float4) + t_m.
        const float4* gsrc = reinterpret_cast<const float4*>(gamma + (size_t)m * DD * DD);
        __syncthreads();  // previous iteration's reads done
        gs[tid] = gsrc[tid];
        gs[tid + 128] = gsrc[tid + 128];
        if (tid < DD / 4) {
            ts[tid] = reinterpret_cast<const float4*>(g_t + m * DD)[tid];
        }
        __syncthreads();

        const float wm = __ldg(&weights[m]);

        float dist = 0.0f;
#pragma unroll
        for (int eg = 0; eg < DD / 4; eg++) {
            float4 t4 = ts[eg];
            float y0 = -t4.x, y1 = -t4.y, y2 = -t4.z, y3 = -t4.w;
#pragma unroll
            for (int d = 0; d < DD; d++) {
                float4 g4 = gs[d * (DD / 4) + eg];
                float xv = xr[d];
                y0 += g4.x * xv;
                y1 += g4.y * xv;
                y2 += g4.z * xv;
                y3 += g4.w * xv;
            }
            dist += y0 * y0 + y1 * y1 + y2 * y2 + y3 * y3;
        }

        acc += wm * __expf(-dist);
    }

    g_partial[blockIdx.y * NN + n] = acc;
}

__global__ void reduce_kernel(float* __restrict__ out) {
    int n = blockIdx.x * blockDim.x + threadIdx.x;
    float s = 0.0f;
#pragma unroll
    for (int i = 0; i < MSPLIT; i++) {
        s += g_partial[i * NN + n];
    }
    out[n] = s;
}

extern "C" void kernel_launch(void* const* d_in, const int* in_sizes, int n_in,
                              void* d_out, int out_size) {
    const float* inputs = (const float*)d_in[0];   // [N, D]
    const float* gamma = (const float*)d_in[1];    // [M, D, D]
    const float* means = (const float*)d_in[2];    // [M, D]
    const float* weights = (const float*)d_in[3];  // [M]
    float* out = (float*)d_out;                    // [N, 1]

    prep_t_kernel<<<MM, DD>>>(gamma, means);
    dim3 grid(NN / BLOCK, MSPLIT);
    rbf_main_kernel<<<grid, BLOCK>>>(inputs, gamma, weights);
    reduce_kernel<<<NN / 256, 256>>>(out);
}

// round 5
// speedup vs baseline: 1.9781x; 1.9781x over previous
#include <cuda_runtime.h>
#include <cuda_bf16.h>
#include <cstdint>

// RBF layer: out[n] = sum_m w[m] * exp(-dist(n,m)),
//   dist = x^T C_m x - 2 x^T C_m mu_m + mu^T C_m mu,  C_m = G_m G_m^T (symmetric)
// N=32768, M=2048, D=32.
//
// Round 5: symmetric-triangle formulation. Per-m packed blob (precomputed):
//   [0:576)   upper triangle of C with off-diag doubled, rows padded to 4-float
//             multiples (row d: len ceil((32-d)/4)*4, zero padded) -> LDS.128
//   [576:608) bm2 = -2 * C mu
//   [608]     c = mu^T C mu
//   [609:640) zero pad
// 592 FFMA per (n,m) instead of 1056. Vanilla instructions only.

#define DD 32
#define NN 32768
#define MM 2048
#define MSPLIT 8
#define BLOCK 128
#define BLOB 640   // floats per m (160 float4)
#define TRI_F4 144 // 576/4

__device__ float g_pack[MM * BLOB];       // packed per-m blobs (5.24 MB)
__device__ float g_partial[MSPLIT * NN];  // partial sums over m-splits

__host__ __device__ constexpr int padlen(int d) { return ((DD - d + 3) / 4) * 4; }
__host__ __device__ constexpr int rowstart(int d) {
    int s = 0;
    for (int k = 0; k < d; k++) s += padlen(k);
    return s;
}

// ---- Kernel 1: build packed blob for each m -------------------------------
__global__ __launch_bounds__(128) void prep_kernel(
    const float* __restrict__ gamma,
    const float* __restrict__ means) {
    __shared__ float Gs[DD * DD];
    __shared__ float Cs[DD * DD];
    __shared__ float mus[DD];
    __shared__ float bs[DD];

    const int m = blockIdx.x;
    const int tid = threadIdx.x;
    float* blob = g_pack + (size_t)m * BLOB;

    // Load G, mu; zero the blob.
    const float* gsrc = gamma + (size_t)m * DD * DD;
#pragma unroll
    for (int i = tid; i < DD * DD; i += 128) Gs[i] = gsrc[i];
    if (tid < DD) mus[tid] = means[(size_t)m * DD + tid];
    for (int i = tid; i < BLOB; i += 128) blob[i] = 0.0f;
    __syncthreads();

    // Upper triangle: 528 entries, strided over 128 threads.
    for (int idx = tid; idx < 528; idx += 128) {
        // map linear idx -> (d, e), rows of length 32-d
        int d = 0, rem = idx;
        while (rem >= DD - d) { rem -= DD - d; d++; }
        int e = d + rem;
        float c = 0.0f;
#pragma unroll
        for (int k = 0; k < DD; k++) c += Gs[d * DD + k] * Gs[e * DD + k];
        Cs[d * DD + e] = c;
        Cs[e * DD + d] = c;
        blob[rowstart(d) + (e - d)] = (e == d) ? c : 2.0f * c;
    }
    __syncthreads();

    // b = C mu ; store bm2 = -2 b
    if (tid < DD) {
        float b = 0.0f;
#pragma unroll
        for (int e = 0; e < DD; e++) b += Cs[tid * DD + e] * mus[e];
        bs[tid] = b;
        blob[576 + tid] = -2.0f * b;
    }
    __syncthreads();

    // c = mu^T C mu = b . mu
    if (tid == 0) {
        float c = 0.0f;
#pragma unroll
        for (int d = 0; d < DD; d++) c += bs[d] * mus[d];
        blob[608] = c;
    }
}

// ---- Kernel 2: main fused kernel ------------------------------------------
__global__ __launch_bounds__(BLOCK) void rbf_main_kernel(
    const float* __restrict__ x,
    const float* __restrict__ weights) {
    __shared__ __align__(16) float4 gs[2][BLOB / 4];  // 2 x 2.5 KB

    const int tid = threadIdx.x;
    const int n = blockIdx.x * BLOCK + tid;
    const int m0 = blockIdx.y * (MM / MSPLIT);
    const int m1 = m0 + (MM / MSPLIT);

    // x row in registers.
    float xr[DD];
    {
        const float4* xp = reinterpret_cast<const float4*>(x + (size_t)n * DD);
#pragma unroll
        for (int i = 0; i < DD / 4; i++) {
            float4 v = xp[i];
            xr[4 * i + 0] = v.x;
            xr[4 * i + 1] = v.y;
            xr[4 * i + 2] = v.z;
            xr[4 * i + 3] = v.w;
        }
    }

    // Prologue: load tile m0 into buffer 0.
    {
        const float4* src = reinterpret_cast<const float4*>(g_pack + (size_t)m0 * BLOB);
        gs[0][tid] = src[tid];
        if (tid < 32) gs[0][128 + tid] = src[128 + tid];
    }
    __syncthreads();

    float acc = 0.0f;

    for (int m = m0; m < m1; ++m) {
        const int buf = (m - m0) & 1;

        // Prefetch next tile into registers (overlaps with compute below).
        float4 p0, p1;
        const bool have_next = (m + 1 < m1);
        if (have_next) {
            const float4* src =
                reinterpret_cast<const float4*>(g_pack + (size_t)(m + 1) * BLOB);
            p0 = src[tid];
            if (tid < 32) p1 = src[128 + tid];
        }

        const float* tile = reinterpret_cast<const float*>(&gs[buf][0]);
        const float4* t4 = reinterpret_cast<const float4*>(tile);
        const float wm = __ldg(&weights[m]);

        float dist = tile[608];  // c term

        // quad: upper-triangle matvec, rows padded & aligned for LDS.128
#pragma unroll
        for (int d = 0; d < DD; d++) {
            float t0 = 0.0f, t1 = 0.0f, t2 = 0.0f, t3 = 0.0f;
            const int ro4 = rowstart(d) / 4;
#pragma unroll
            for (int g = 0; g < padlen(d) / 4; g++) {
                float4 v = t4[ro4 + g];
                const int e0 = d + 4 * g;
                t0 += v.x * xr[e0];
                if (e0 + 1 < DD) t1 += v.y * xr[e0 + 1];
                if (e0 + 2 < DD) t2 += v.z * xr[e0 + 2];
                if (e0 + 3 < DD) t3 += v.w * xr[e0 + 3];
            }
            dist += xr[d] * ((t0 + t1) + (t2 + t3));
        }

        // cross: x . bm2  (bm2 = -2 C mu)
#pragma unroll
        for (int g = 0; g < DD / 4; g++) {
            float4 v = t4[TRI_F4 + g];
            dist += v.x * xr[4 * g] + v.y * xr[4 * g + 1] + v.z * xr[4 * g + 2] +
                    v.w * xr[4 * g + 3];
        }

        acc += wm * __expf(-dist);

        // Store prefetched tile into the other buffer.
        if (have_next) {
            __syncthreads();  // everyone done reading buf^1 (tile m-1)
            gs[buf ^ 1][tid] = p0;
            if (tid < 32) gs[buf ^ 1][128 + tid] = p1;
            __syncthreads();
        }
    }

    g_partial[blockIdx.y * NN + n] = acc;
}

// ---- Kernel 3: reduce partials --------------------------------------------
__global__ void reduce_kernel(float* __restrict__ out) {
    int n = blockIdx.x * blockDim.x + threadIdx.x;
    float s = 0.0f;
#pragma unroll
    for (int i = 0; i < MSPLIT; i++) s += g_partial[i * NN + n];
    out[n] = s;
}

extern "C" void kernel_launch(void* const* d_in, const int* in_sizes, int n_in,
                              void* d_out, int out_size) {
    const float* inputs = (const float*)d_in[0];   // [N, D]
    const float* gamma = (const float*)d_in[1];    // [M, D, D]
    const float* means = (const float*)d_in[2];    // [M, D]
    const float* weights = (const float*)d_in[3];  // [M]
    float* out = (float*)d_out;                    // [N, 1]

    prep_kernel<<<MM, 128>>>(gamma, means);
    dim3 grid(NN / BLOCK, MSPLIT);
    rbf_main_kernel<<<grid, BLOCK>>>(inputs, weights);
    reduce_kernel<<<NN / 256, 256>>>(out);
}